// round 3
// baseline (speedup 1.0000x reference)
#include <cuda_runtime.h>
#include <cuda_fp16.h>
#include <cstdint>

// ============================ problem sizes ============================
#define BB    32
#define CIN   256
#define COUT  512
#define HWSZ  4096                  // 64*64
#define KTOT  256
#define NPIX  131072.0f             // B*H*W per channel

// ============================ device scratch ============================
__device__ __align__(128) float  g_noise[CIN * HWSZ];            // 4 MB
__device__ __align__(128) __half g_w[COUT * KTOT];               // 256 KB  [o][c]
__device__ __align__(128) __half g_y[(size_t)BB * COUT * HWSZ];  // 134 MB
__device__ float g_sum[COUT];
__device__ float g_sq[COUT];

// ============================ helpers ============================
__device__ __forceinline__ uint32_t smem_u32(const void* p) {
    uint32_t a;
    asm("{ .reg .u64 t; cvta.to.shared.u64 t, %1; cvt.u32.u64 %0, t; }" : "=r"(a) : "l"(p));
    return a;
}
__device__ __forceinline__ void ldsm_x4(uint32_t& r0, uint32_t& r1, uint32_t& r2, uint32_t& r3,
                                        uint32_t addr) {
    asm volatile("ldmatrix.sync.aligned.m8n8.x4.shared.b16 {%0,%1,%2,%3}, [%4];"
                 : "=r"(r0), "=r"(r1), "=r"(r2), "=r"(r3) : "r"(addr));
}
__device__ __forceinline__ void ldsm_x4_t(uint32_t& r0, uint32_t& r1, uint32_t& r2, uint32_t& r3,
                                          uint32_t addr) {
    asm volatile("ldmatrix.sync.aligned.m8n8.x4.trans.shared.b16 {%0,%1,%2,%3}, [%4];"
                 : "=r"(r0), "=r"(r1), "=r"(r2), "=r"(r3) : "r"(addr));
}
__device__ __forceinline__ void mma16816(float* d, const uint32_t* a, uint32_t b0, uint32_t b1) {
    asm volatile("mma.sync.aligned.m16n8k16.row.col.f32.f16.f16.f32 "
                 "{%0,%1,%2,%3}, {%4,%5,%6,%7}, {%8,%9}, {%0,%1,%2,%3};"
                 : "+f"(d[0]), "+f"(d[1]), "+f"(d[2]), "+f"(d[3])
                 : "r"(a[0]), "r"(a[1]), "r"(a[2]), "r"(a[3]), "r"(b0), "r"(b1));
}

// ============================ kernel 0: init ============================
// LCG jump-ahead: s -> 65539*s + 1 (mod 2^32); noise[i] = float(seed after i+1 steps) * (0.1/RAND_MAX)
__global__ void k_init(const float* __restrict__ w) {
    int i = blockIdx.x * blockDim.x + threadIdx.x;   // 0 .. 1048575
    unsigned n = (unsigned)i + 1u;
    unsigned rA = 1u, rC = 0u, bA = 65539u, bC = 1u;
    while (n) {
        if (n & 1u) { rC = bA * rC + bC; rA = bA * rA; }
        unsigned nbC = bA * bC + bC;
        bA = bA * bA; bC = nbC;
        n >>= 1;
    }
    unsigned seed = rA * 12345u + rC;
    g_noise[i] = (float)seed * (float)(0.1 / 4294967295.0);

    if (i < COUT * KTOT) g_w[i] = __float2half_rn(w[i]);
    if (i < COUT) { g_sum[i] = 0.0f; g_sq[i] = 0.0f; }
}

// ============================ kernel 1: fused GEMM ============================
// CTA computes D[128 m-pixels][128 out-channels]. A tile built on the fly:
// relu(x+noise) -> fp16 smem [k][m]. B = g_w resident in smem [n][k] full K.
// Epilogue: per-channel sum/sumsq (BN stats) + y fp16 store.
#define SMB_OFF   0                    // [128][264] half = 67584 B
#define SMA_OFF   67584                // [64][136]  half = 17408 B
#define STAT_OFF  84992                // 2 * 128 floats = 1024 B
#define SM_TOTAL  86016
#define SMB_STRIDE 264                 // halves per n row (+8 pad)
#define SMA_STRIDE 136                 // halves per k row (+8 pad)

__global__ void __launch_bounds__(256) k_gemm(const float* __restrict__ x) {
    extern __shared__ char smem[];
    __half* smB = (__half*)(smem + SMB_OFF);
    __half* smA = (__half*)(smem + SMA_OFF);
    float*  sums = (float*)(smem + STAT_OFF);
    float*  sqs  = sums + 128;
    uint32_t smB_u = smem_u32(smB);
    uint32_t smA_u = smem_u32(smA);

    int tid = threadIdx.x, warp = tid >> 5, lane = tid & 31;
    int bidx = blockIdx.x;
    int ntile = bidx & 3;            // 4 N-tiles share an A tile -> adjacent for L2 reuse
    int mtile = bidx >> 2;           // 0..1023
    int b   = mtile >> 5;            // 32 m-tiles per batch image
    int hw0 = (mtile & 31) << 7;     // 128-pixel slab, contiguous in hw

    if (tid < 128) { sums[tid] = 0.0f; sqs[tid] = 0.0f; }

    // ---- load full B tile [128 n][256 k] fp16 (resident all K) ----
    {
        int n = tid >> 1, seg = tid & 1;
        const uint4* src = (const uint4*)(g_w + (size_t)(ntile * 128 + n) * KTOT + seg * 128);
        uint4* dst = (uint4*)(smB + n * SMB_STRIDE + seg * 128);
        #pragma unroll
        for (int i = 0; i < 16; i++) dst[i] = src[i];
    }

    int mw = (warp >> 2) * 64;       // warp m offset (2 rows of warps)
    int nw = (warp & 3) * 32;        // warp n offset (4 cols of warps)

    float acc[16][4];
    #pragma unroll
    for (int i = 0; i < 16; i++)
        #pragma unroll
        for (int j = 0; j < 4; j++) acc[i][j] = 0.0f;

    // ldmatrix per-lane base addresses
    // A (trans, smA is [k][m]): idx=lane>>3; koff=(lane>>4)*8; moff=((lane>>3)&1)*8
    uint32_t aaddr = smA_u + (uint32_t)(((lane & 7) + ((lane >> 4) << 3)) * SMA_STRIDE
                                        + mw + ((lane >> 3) & 1) * 8) * 2u;
    // B (non-trans, smB is [n][k]): noff=(lane>>4)*8; koff=((lane>>3)&1)*8
    uint32_t baddr = smB_u + (uint32_t)((nw + (lane & 7) + ((lane >> 4) << 3)) * SMB_STRIDE) * 2u
                           + (uint32_t)(((lane >> 3) & 1) * 8) * 2u;

    // ---- main loop: K in 4 chunks of 64 ----
    for (int kc = 0; kc < 4; kc++) {
        __syncthreads();             // smA free for reuse
        // stage relu(x+noise) chunk -> fp16 smA[k_local][m]
        int cl = warp * 8;           // 8 channels per warp
        #pragma unroll
        for (int r = 0; r < 8; r++) {
            int c = kc * 64 + cl + r;
            size_t off = ((size_t)(b * CIN + c)) * HWSZ + hw0 + lane * 4;
            float4 xv = *(const float4*)(x + off);
            float4 nv = *(const float4*)(g_noise + (size_t)c * HWSZ + hw0 + lane * 4);
            float v0 = fmaxf(xv.x + nv.x, 0.0f);
            float v1 = fmaxf(xv.y + nv.y, 0.0f);
            float v2 = fmaxf(xv.z + nv.z, 0.0f);
            float v3 = fmaxf(xv.w + nv.w, 0.0f);
            __half2 h01 = __floats2half2_rn(v0, v1);
            __half2 h23 = __floats2half2_rn(v2, v3);
            uint2 pack;
            pack.x = *(uint32_t*)&h01;
            pack.y = *(uint32_t*)&h23;
            *(uint2*)(smA + (cl + r) * SMA_STRIDE + lane * 4) = pack;
        }
        __syncthreads();

        #pragma unroll
        for (int ks = 0; ks < 4; ks++) {
            uint32_t afr[4][4];
            #pragma unroll
            for (int mi = 0; mi < 4; mi++)
                ldsm_x4_t(afr[mi][0], afr[mi][1], afr[mi][2], afr[mi][3],
                          aaddr + (uint32_t)(ks * 16 * SMA_STRIDE + mi * 16) * 2u);
            uint32_t bfr[2][4];
            #pragma unroll
            for (int nip = 0; nip < 2; nip++)
                ldsm_x4(bfr[nip][0], bfr[nip][1], bfr[nip][2], bfr[nip][3],
                        baddr + (uint32_t)(nip * 16 * SMB_STRIDE + (kc * 64 + ks * 16)) * 2u);
            #pragma unroll
            for (int mi = 0; mi < 4; mi++)
                #pragma unroll
                for (int ni = 0; ni < 4; ni++)
                    mma16816(acc[mi * 4 + ni], afr[mi],
                             bfr[ni >> 1][(ni & 1) * 2], bfr[ni >> 1][(ni & 1) * 2 + 1]);
        }
    }

    // ---- epilogue: stats + y fp16 via smem transpose ----
    __syncthreads();                         // everyone done reading smB/smA
    __half* smY = (__half*)smem;             // [128 n][136 m] halves (34816 B, reuses smB)
    int g = lane >> 2, t = lane & 3;
    float lsum[8], lsq[8];
    #pragma unroll
    for (int j = 0; j < 8; j++) { lsum[j] = 0.0f; lsq[j] = 0.0f; }

    #pragma unroll
    for (int mi = 0; mi < 4; mi++) {
        #pragma unroll
        for (int ni = 0; ni < 4; ni++) {
            float c0 = acc[mi * 4 + ni][0], c1 = acc[mi * 4 + ni][1];
            float c2 = acc[mi * 4 + ni][2], c3 = acc[mi * 4 + ni][3];
            int m0 = mw + mi * 16 + g;               // c0,c1 at m0; c2,c3 at m0+8
            int n0 = nw + ni * 8 + t * 2;            // c0,c2 at n0; c1,c3 at n0+1
            smY[n0 * SMA_STRIDE + m0]           = __float2half_rn(c0);
            smY[(n0 + 1) * SMA_STRIDE + m0]     = __float2half_rn(c1);
            smY[n0 * SMA_STRIDE + m0 + 8]       = __float2half_rn(c2);
            smY[(n0 + 1) * SMA_STRIDE + m0 + 8] = __float2half_rn(c3);
            int j0 = ni * 2;
            lsum[j0]     += c0 + c2;  lsq[j0]     += c0 * c0 + c2 * c2;
            lsum[j0 + 1] += c1 + c3;  lsq[j0 + 1] += c1 * c1 + c3 * c3;
        }
    }
    // reduce over the 8 m-lanes (groupID bits = lane bits 2..4)
    #pragma unroll
    for (int j = 0; j < 8; j++) {
        #pragma unroll
        for (int off = 4; off <= 16; off <<= 1) {
            lsum[j] += __shfl_xor_sync(0xFFFFFFFFu, lsum[j], off);
            lsq[j]  += __shfl_xor_sync(0xFFFFFFFFu, lsq[j], off);
        }
    }
    if (g == 0) {
        #pragma unroll
        for (int j = 0; j < 8; j++) {
            int n = nw + (j >> 1) * 8 + t * 2 + (j & 1);
            atomicAdd(&sums[n], lsum[j]);
            atomicAdd(&sqs[n],  lsq[j]);
        }
    }
    __syncthreads();

    // coalesced y store: each warp writes 16 n-rows, 128 contiguous hw halves each
    #pragma unroll
    for (int i = 0; i < 16; i++) {
        int n = warp * 16 + i;
        uint2 v = *(uint2*)(smY + n * SMA_STRIDE + lane * 4);
        *(uint2*)(g_y + ((size_t)(b * COUT + ntile * 128 + n)) * HWSZ + hw0 + lane * 4) = v;
    }
    if (tid < 128) {
        atomicAdd(&g_sum[ntile * 128 + tid], sums[tid]);
        atomicAdd(&g_sq[ntile * 128 + tid],  sqs[tid]);
    }
}

// ============================ kernel 2: BN normalize ============================
__global__ void k_norm(float* __restrict__ out,
                       const float* __restrict__ gamma,
                       const float* __restrict__ beta) {
    size_t idx4 = (size_t)blockIdx.x * blockDim.x + threadIdx.x;  // 16,777,216 float4s
    int o = (int)((idx4 >> 10) & (COUT - 1));
    float mean = g_sum[o] * (1.0f / NPIX);
    float var  = g_sq[o]  * (1.0f / NPIX) - mean * mean;
    float inv  = rsqrtf(var + 1e-5f);
    float ga = gamma[o] * inv;
    float be = beta[o] - mean * ga;
    uint2 p = *(const uint2*)(g_y + idx4 * 4);
    __half2 h0 = *(__half2*)&p.x;
    __half2 h1 = *(__half2*)&p.y;
    float2 f0 = __half22float2(h0);
    float2 f1 = __half22float2(h1);
    float4 o4;
    o4.x = f0.x * ga + be;
    o4.y = f0.y * ga + be;
    o4.z = f1.x * ga + be;
    o4.w = f1.y * ga + be;
    ((float4*)out)[idx4] = o4;
}

// ============================ launcher ============================
extern "C" void kernel_launch(void* const* d_in, const int* in_sizes, int n_in,
                              void* d_out, int out_size) {
    const float* x     = (const float*)d_in[0];
    const float* w     = (const float*)d_in[1];
    // d_in[2] = conv_b: exactly cancelled by BatchNorm mean subtraction.
    const float* gamma = (const float*)d_in[3];
    const float* beta  = (const float*)d_in[4];
    float* out = (float*)d_out;

    cudaFuncSetAttribute(k_gemm, cudaFuncAttributeMaxDynamicSharedMemorySize, SM_TOTAL);

    k_init<<<4096, 256>>>(w);                 // noise table + fp16 W + zero stats
    k_gemm<<<4096, 256, SM_TOTAL>>>(x);       // fused noise+relu+GEMM+BN-stats, y fp16
    k_norm<<<65536, 256>>>(out, gamma, beta); // finalize BN -> fp32 out
}

// round 5
// speedup vs baseline: 1.0699x; 1.0699x over previous
#include <cuda_runtime.h>
#include <cuda_fp16.h>
#include <cstdint>

// ============================ problem sizes ============================
#define BB    32
#define CIN   256
#define COUT  512
#define HWSZ  4096                  // 64*64
#define KTOT  256
#define NPIX  131072.0f             // B*H*W per channel

// ============================ device scratch ============================
__device__ __align__(128) float  g_noise[CIN * HWSZ];            // 4 MB
__device__ __align__(128) __half g_w[COUT * KTOT];               // 256 KB  [o][c]
__device__ __align__(128) __half g_y[(size_t)BB * COUT * HWSZ];  // 134 MB
__device__ float g_sum[COUT];
__device__ float g_sq[COUT];

// ============================ helpers ============================
__device__ __forceinline__ uint32_t smem_u32(const void* p) {
    uint32_t a;
    asm("{ .reg .u64 t; cvta.to.shared.u64 t, %1; cvt.u32.u64 %0, t; }" : "=r"(a) : "l"(p));
    return a;
}
__device__ __forceinline__ void ldsm_x4(uint32_t& r0, uint32_t& r1, uint32_t& r2, uint32_t& r3,
                                        uint32_t addr) {
    asm volatile("ldmatrix.sync.aligned.m8n8.x4.shared.b16 {%0,%1,%2,%3}, [%4];"
                 : "=r"(r0), "=r"(r1), "=r"(r2), "=r"(r3) : "r"(addr));
}
__device__ __forceinline__ void ldsm_x4_t(uint32_t& r0, uint32_t& r1, uint32_t& r2, uint32_t& r3,
                                          uint32_t addr) {
    asm volatile("ldmatrix.sync.aligned.m8n8.x4.trans.shared.b16 {%0,%1,%2,%3}, [%4];"
                 : "=r"(r0), "=r"(r1), "=r"(r2), "=r"(r3) : "r"(addr));
}
__device__ __forceinline__ void mma16816(float* d, const uint32_t* a, uint32_t b0, uint32_t b1) {
    asm volatile("mma.sync.aligned.m16n8k16.row.col.f32.f16.f16.f32 "
                 "{%0,%1,%2,%3}, {%4,%5,%6,%7}, {%8,%9}, {%0,%1,%2,%3};"
                 : "+f"(d[0]), "+f"(d[1]), "+f"(d[2]), "+f"(d[3])
                 : "r"(a[0]), "r"(a[1]), "r"(a[2]), "r"(a[3]), "r"(b0), "r"(b1));
}

// ============================ kernel 0: init ============================
// LCG s -> 65539*s + 1 (mod 2^32); noise[i] = float(seed after i+1 steps) * 0.1/RAND_MAX.
// Per-bit affine jump constants are thread-independent -> compile-time immediates.
struct LCGTab { unsigned A[21]; unsigned C[21]; };
__host__ __device__ constexpr LCGTab make_tab() {
    LCGTab t{};
    unsigned a = 65539u, c = 1u;
    for (int j = 0; j < 21; j++) {
        t.A[j] = a; t.C[j] = c;
        unsigned c2 = a * c + c;
        a = a * a; c = c2;
    }
    return t;
}
__global__ void k_init(const float* __restrict__ w) {
    constexpr LCGTab T = make_tab();
    int i = blockIdx.x * blockDim.x + threadIdx.x;   // 0 .. 1048575
    unsigned n = (unsigned)i + 1u;                   // 1 .. 2^20
    unsigned rA = 1u, rC = 0u;
    #pragma unroll
    for (int j = 0; j < 21; j++) {
        if ((n >> j) & 1u) { rA = T.A[j] * rA; rC = T.A[j] * rC + T.C[j]; }
    }
    unsigned seed = rA * 12345u + rC;
    g_noise[i] = (float)seed * (float)(0.1 / 4294967295.0);

    if (i < COUT * KTOT) g_w[i] = __float2half_rn(w[i]);
    if (i < COUT) { g_sum[i] = 0.0f; g_sq[i] = 0.0f; }
}

// ============================ kernel 1: fused, pipelined GEMM ============================
// CTA: D[128 m-pixels][128 out-channels]. A built on the fly (relu(x+noise) -> fp16),
// double-buffered in smem; next chunk's x+noise prefetched into regs BEFORE the MMA
// phase so DRAM latency hides under HMMA. Epilogue: BN stats + y fp16 store.
#define SMB_OFF    0                    // [128][264] half = 67584 B
#define SMA0_OFF   67584                // [64][136]  half = 17408 B
#define SMA1_OFF   84992
#define STAT_OFF   102400               // 2 * 128 floats
#define SM_TOTAL   103424
#define SMB_STRIDE 264                  // halves per n row (+8 pad)
#define SMA_STRIDE 136                  // halves per k row (+8 pad)

__global__ void __launch_bounds__(256, 1) k_gemm(const float* __restrict__ x) {
    extern __shared__ char smem[];
    __half* smB  = (__half*)(smem + SMB_OFF);
    __half* smA0 = (__half*)(smem + SMA0_OFF);
    __half* smA1 = (__half*)(smem + SMA1_OFF);
    float*  sums = (float*)(smem + STAT_OFF);
    float*  sqs  = sums + 128;
    uint32_t smB_u  = smem_u32(smB);
    uint32_t smA0_u = smem_u32(smA0);
    uint32_t smA1_u = smem_u32(smA1);

    int tid = threadIdx.x, warp = tid >> 5, lane = tid & 31;
    int bidx = blockIdx.x;
    int ntile = bidx & 3;            // 4 N-tiles share an A slab -> L2 reuse of x
    int mtile = bidx >> 2;
    int b   = mtile >> 5;
    int hw0 = (mtile & 31) << 7;     // 128-pixel contiguous hw slab

    if (tid < 128) { sums[tid] = 0.0f; sqs[tid] = 0.0f; }

    // ---- B tile [128 n][256 k] fp16, resident full-K ----
    {
        int n = tid >> 1, seg = tid & 1;
        const uint4* src = (const uint4*)(g_w + (size_t)(ntile * 128 + n) * KTOT + seg * 128);
        uint4* dst = (uint4*)(smB + n * SMB_STRIDE + seg * 128);
        #pragma unroll
        for (int i = 0; i < 16; i++) dst[i] = src[i];
    }

    int mw = (warp >> 2) * 64;       // warp m offset
    int nw = (warp & 3) * 32;        // warp n offset
    int cl = warp * 8;               // 8 channels staged per warp per chunk

    float acc[16][4];
    #pragma unroll
    for (int i = 0; i < 16; i++)
        #pragma unroll
        for (int j = 0; j < 4; j++) acc[i][j] = 0.0f;

    // ldmatrix lane base offsets
    uint32_t a_lane = (uint32_t)(((lane & 7) + ((lane >> 4) << 3)) * SMA_STRIDE
                                 + mw + ((lane >> 3) & 1) * 8) * 2u;
    uint32_t aaddr0 = smA0_u + a_lane;
    uint32_t aaddr1 = smA1_u + a_lane;
    uint32_t baddr  = smB_u + (uint32_t)((nw + (lane & 7) + ((lane >> 4) << 3)) * SMB_STRIDE) * 2u
                            + (uint32_t)(((lane >> 3) & 1) * 8) * 2u;

    // ---- prologue: stage chunk 0 into smA0 ----
    {
        #pragma unroll
        for (int r = 0; r < 8; r++) {
            int c = cl + r;
            float4 xv = *(const float4*)(x + ((size_t)(b * CIN + c)) * HWSZ + hw0 + lane * 4);
            float4 nv = *(const float4*)(g_noise + (size_t)c * HWSZ + hw0 + lane * 4);
            __half2 h01 = __floats2half2_rn(fmaxf(xv.x + nv.x, 0.0f), fmaxf(xv.y + nv.y, 0.0f));
            __half2 h23 = __floats2half2_rn(fmaxf(xv.z + nv.z, 0.0f), fmaxf(xv.w + nv.w, 0.0f));
            uint2 pack;
            pack.x = *(uint32_t*)&h01;
            pack.y = *(uint32_t*)&h23;
            *(uint2*)(smA0 + (cl + r) * SMA_STRIDE + lane * 4) = pack;
        }
    }
    __syncthreads();

    // ---- main loop, pipelined ----
    float4 xr[8], nr[8];
    #pragma unroll
    for (int kc = 0; kc < 4; kc++) {
        // prefetch next chunk (issued before MMA; consumed after the sync)
        if (kc < 3) {
            #pragma unroll
            for (int r = 0; r < 8; r++) {
                int c = (kc + 1) * 64 + cl + r;
                xr[r] = *(const float4*)(x + ((size_t)(b * CIN + c)) * HWSZ + hw0 + lane * 4);
                nr[r] = *(const float4*)(g_noise + (size_t)c * HWSZ + hw0 + lane * 4);
            }
        }

        uint32_t aaddr = (kc & 1) ? aaddr1 : aaddr0;
        #pragma unroll
        for (int ks = 0; ks < 4; ks++) {
            uint32_t afr[4][4];
            #pragma unroll
            for (int mi = 0; mi < 4; mi++)
                ldsm_x4_t(afr[mi][0], afr[mi][1], afr[mi][2], afr[mi][3],
                          aaddr + (uint32_t)(ks * 16 * SMA_STRIDE + mi * 16) * 2u);
            uint32_t bfr[2][4];
            #pragma unroll
            for (int nip = 0; nip < 2; nip++)
                ldsm_x4(bfr[nip][0], bfr[nip][1], bfr[nip][2], bfr[nip][3],
                        baddr + (uint32_t)(nip * 16 * SMB_STRIDE + (kc * 64 + ks * 16)) * 2u);
            #pragma unroll
            for (int mi = 0; mi < 4; mi++)
                #pragma unroll
                for (int ni = 0; ni < 4; ni++)
                    mma16816(acc[mi * 4 + ni], afr[mi],
                             bfr[ni >> 1][(ni & 1) * 2], bfr[ni >> 1][(ni & 1) * 2 + 1]);
        }
        __syncthreads();                       // all warps done reading smA[kc&1] / (last: smB)

        if (kc < 3) {
            __half* nxt = (kc & 1) ? smA0 : smA1;
            #pragma unroll
            for (int r = 0; r < 8; r++) {
                __half2 h01 = __floats2half2_rn(fmaxf(xr[r].x + nr[r].x, 0.0f),
                                                fmaxf(xr[r].y + nr[r].y, 0.0f));
                __half2 h23 = __floats2half2_rn(fmaxf(xr[r].z + nr[r].z, 0.0f),
                                                fmaxf(xr[r].w + nr[r].w, 0.0f));
                uint2 pack;
                pack.x = *(uint32_t*)&h01;
                pack.y = *(uint32_t*)&h23;
                *(uint2*)(nxt + (cl + r) * SMA_STRIDE + lane * 4) = pack;
            }
            __syncthreads();
        }
    }

    // ---- epilogue: BN stats + y fp16 via smem transpose (smY overlays smB) ----
    __half* smY = (__half*)smem;             // [128 n][136 m] halves
    int g = lane >> 2, t = lane & 3;
    float lsum[8], lsq[8];
    #pragma unroll
    for (int j = 0; j < 8; j++) { lsum[j] = 0.0f; lsq[j] = 0.0f; }

    #pragma unroll
    for (int mi = 0; mi < 4; mi++) {
        #pragma unroll
        for (int ni = 0; ni < 4; ni++) {
            float c0 = acc[mi * 4 + ni][0], c1 = acc[mi * 4 + ni][1];
            float c2 = acc[mi * 4 + ni][2], c3 = acc[mi * 4 + ni][3];
            int m0 = mw + mi * 16 + g;
            int n0 = nw + ni * 8 + t * 2;
            smY[n0 * SMA_STRIDE + m0]           = __float2half_rn(c0);
            smY[(n0 + 1) * SMA_STRIDE + m0]     = __float2half_rn(c1);
            smY[n0 * SMA_STRIDE + m0 + 8]       = __float2half_rn(c2);
            smY[(n0 + 1) * SMA_STRIDE + m0 + 8] = __float2half_rn(c3);
            int j0 = ni * 2;
            lsum[j0]     += c0 + c2;  lsq[j0]     += c0 * c0 + c2 * c2;
            lsum[j0 + 1] += c1 + c3;  lsq[j0 + 1] += c1 * c1 + c3 * c3;
        }
    }
    #pragma unroll
    for (int j = 0; j < 8; j++) {
        #pragma unroll
        for (int off = 4; off <= 16; off <<= 1) {
            lsum[j] += __shfl_xor_sync(0xFFFFFFFFu, lsum[j], off);
            lsq[j]  += __shfl_xor_sync(0xFFFFFFFFu, lsq[j], off);
        }
    }
    if (g == 0) {
        #pragma unroll
        for (int j = 0; j < 8; j++) {
            int n = nw + (j >> 1) * 8 + t * 2 + (j & 1);
            atomicAdd(&sums[n], lsum[j]);
            atomicAdd(&sqs[n],  lsq[j]);
        }
    }
    __syncthreads();

    #pragma unroll
    for (int i = 0; i < 16; i++) {
        int n = warp * 16 + i;
        uint2 v = *(uint2*)(smY + n * SMA_STRIDE + lane * 4);
        *(uint2*)(g_y + ((size_t)(b * COUT + ntile * 128 + n)) * HWSZ + hw0 + lane * 4) = v;
    }
    if (tid < 128) {
        atomicAdd(&g_sum[ntile * 128 + tid], sums[tid]);
        atomicAdd(&g_sq[ntile * 128 + tid],  sqs[tid]);
    }
}

// ============================ kernel 2: BN normalize ============================
__global__ void k_norm(float* __restrict__ out,
                       const float* __restrict__ gamma,
                       const float* __restrict__ beta) {
    size_t idx4 = (size_t)blockIdx.x * blockDim.x + threadIdx.x;  // 16,777,216 float4s
    int o = (int)((idx4 >> 10) & (COUT - 1));
    float mean = g_sum[o] * (1.0f / NPIX);
    float var  = g_sq[o]  * (1.0f / NPIX) - mean * mean;
    float inv  = rsqrtf(var + 1e-5f);
    float ga = gamma[o] * inv;
    float be = beta[o] - mean * ga;
    uint2 p = __ldcs((const uint2*)(g_y + idx4 * 4));   // streaming read, no reuse
    __half2 h0 = *(__half2*)&p.x;
    __half2 h1 = *(__half2*)&p.y;
    float2 f0 = __half22float2(h0);
    float2 f1 = __half22float2(h1);
    float4 o4;
    o4.x = f0.x * ga + be;
    o4.y = f0.y * ga + be;
    o4.z = f1.x * ga + be;
    o4.w = f1.y * ga + be;
    __stcs(((float4*)out) + idx4, o4);                  // streaming write
}

// ============================ launcher ============================
extern "C" void kernel_launch(void* const* d_in, const int* in_sizes, int n_in,
                              void* d_out, int out_size) {
    const float* x     = (const float*)d_in[0];
    const float* w     = (const float*)d_in[1];
    // d_in[2] = conv_b: exactly cancelled by BatchNorm mean subtraction.
    const float* gamma = (const float*)d_in[3];
    const float* beta  = (const float*)d_in[4];
    float* out = (float*)d_out;

    cudaFuncSetAttribute(k_gemm, cudaFuncAttributeMaxDynamicSharedMemorySize, SM_TOTAL);

    k_init<<<4096, 256>>>(w);                 // noise table + fp16 W + zero stats
    k_gemm<<<4096, 256, SM_TOTAL>>>(x);       // fused noise+relu+GEMM+BN-stats, y fp16
    k_norm<<<65536, 256>>>(out, gamma, beta); // finalize BN -> fp32 out
}

// round 7
// speedup vs baseline: 1.1697x; 1.0933x over previous
#include <cuda_runtime.h>
#include <cuda_fp16.h>
#include <cstdint>

// ============================ problem sizes ============================
#define BB    32
#define CIN   256
#define COUT  512
#define HWSZ  4096                  // 64*64
#define KTOT  256
#define NPIX  131072.0f             // B*H*W per channel

// ============================ device scratch ============================
__device__ __align__(128) float  g_noise[CIN * HWSZ];            // 4 MB
__device__ __align__(128) __half g_w[COUT * KTOT];               // 256 KB  [o][c]
__device__ __align__(128) __half g_y[(size_t)BB * COUT * HWSZ];  // 134 MB
__device__ float g_sum[COUT];
__device__ float g_sq[COUT];

// ============================ helpers ============================
__device__ __forceinline__ uint32_t smem_u32(const void* p) {
    uint32_t a;
    asm("{ .reg .u64 t; cvta.to.shared.u64 t, %1; cvt.u32.u64 %0, t; }" : "=r"(a) : "l"(p));
    return a;
}
__device__ __forceinline__ void ldsm_x4(uint32_t& r0, uint32_t& r1, uint32_t& r2, uint32_t& r3,
                                        uint32_t addr) {
    asm volatile("ldmatrix.sync.aligned.m8n8.x4.shared.b16 {%0,%1,%2,%3}, [%4];"
                 : "=r"(r0), "=r"(r1), "=r"(r2), "=r"(r3) : "r"(addr));
}
__device__ __forceinline__ void ldsm_x4_t(uint32_t& r0, uint32_t& r1, uint32_t& r2, uint32_t& r3,
                                          uint32_t addr) {
    asm volatile("ldmatrix.sync.aligned.m8n8.x4.trans.shared.b16 {%0,%1,%2,%3}, [%4];"
                 : "=r"(r0), "=r"(r1), "=r"(r2), "=r"(r3) : "r"(addr));
}
__device__ __forceinline__ void mma16816(float* d, const uint32_t* a, uint32_t b0, uint32_t b1) {
    asm volatile("mma.sync.aligned.m16n8k16.row.col.f32.f16.f16.f32 "
                 "{%0,%1,%2,%3}, {%4,%5,%6,%7}, {%8,%9}, {%0,%1,%2,%3};"
                 : "+f"(d[0]), "+f"(d[1]), "+f"(d[2]), "+f"(d[3])
                 : "r"(a[0]), "r"(a[1]), "r"(a[2]), "r"(a[3]), "r"(b0), "r"(b1));
}

// ============================ kernel 0: init ============================
struct LCGTab { unsigned A[21]; unsigned C[21]; };
__host__ __device__ constexpr LCGTab make_tab() {
    LCGTab t{};
    unsigned a = 65539u, c = 1u;
    for (int j = 0; j < 21; j++) {
        t.A[j] = a; t.C[j] = c;
        unsigned c2 = a * c + c;
        a = a * a; c = c2;
    }
    return t;
}
__global__ void k_init(const float* __restrict__ w) {
    constexpr LCGTab T = make_tab();
    int i = blockIdx.x * blockDim.x + threadIdx.x;   // 0 .. 1048575
    unsigned n = (unsigned)i + 1u;
    unsigned rA = 1u, rC = 0u;
    #pragma unroll
    for (int j = 0; j < 21; j++) {
        if ((n >> j) & 1u) { rA = T.A[j] * rA; rC = T.A[j] * rC + T.C[j]; }
    }
    unsigned seed = rA * 12345u + rC;
    g_noise[i] = (float)seed * (float)(0.1 / 4294967295.0);

    if (i < COUT * KTOT) g_w[i] = __float2half_rn(w[i]);
    if (i < COUT) { g_sum[i] = 0.0f; g_sq[i] = 0.0f; }
}

// ============================ kernel 1: fused GEMM v2 ============================
// CTA: 128 m-pixels x ALL 512 out-channels (4 internal n-tiles of 128).
// A = relu(x+noise) fp16, FULL-K resident in smem (x read from DRAM exactly once),
// staged chunk-by-chunk pipelined under ntile-0's MMA. B streams from L2 through a
// double buffer with register prefetch. Per-ntile epilogue: BN stats + fp16 y.
#define SMA_OFF    0                       // [256 k][136 m] half = 69632 B
#define SMB_OFF    69632                   // 2 x [128 n][72 k] half = 36864 B
#define SMY_OFF    106496                  // [128 n][136 m] half = 34816 B
#define STAT_OFF   141312                  // 256 floats
#define SM_TOTAL   142336
#define SMA_STRIDE 136
#define SMB_STRIDE 72
#define SMB_BUF_H  9216                    // halves per B buffer (128*72)

__global__ void __launch_bounds__(256, 1) k_gemm(const float* __restrict__ x) {
    extern __shared__ char smem[];
    __half* smA = (__half*)(smem + SMA_OFF);
    __half* smB = (__half*)(smem + SMB_OFF);
    __half* smY = (__half*)(smem + SMY_OFF);
    float*  sums = (float*)(smem + STAT_OFF);
    float*  sqs  = sums + 128;
    uint32_t smA_u = smem_u32(smA);
    uint32_t smB_u = smem_u32(smB);

    int tid = threadIdx.x, warp = tid >> 5, lane = tid & 31;
    int mtile = blockIdx.x;            // 0..1023
    int b   = mtile >> 5;
    int hw0 = (mtile & 31) << 7;       // 128-pixel contiguous hw slab

    int mw = (warp >> 2) * 64;         // warp m offset
    int nw = (warp & 3) * 32;          // warp n offset within 128-n tile
    int cl = warp * 8;                 // channels staged per warp per chunk

    // B load mapping: thread -> (row, 32-half part)
    int brow = tid & 127, bpart = tid >> 7;

    // ---- prologue: stage A chunk 0 + B(ntile0, kc0) ----
    #pragma unroll
    for (int r = 0; r < 8; r++) {
        int c = cl + r;
        float4 xv = *(const float4*)(x + ((size_t)(b * CIN + c)) * HWSZ + hw0 + lane * 4);
        float4 nv = *(const float4*)(g_noise + (size_t)c * HWSZ + hw0 + lane * 4);
        __half2 h01 = __floats2half2_rn(fmaxf(xv.x + nv.x, 0.0f), fmaxf(xv.y + nv.y, 0.0f));
        __half2 h23 = __floats2half2_rn(fmaxf(xv.z + nv.z, 0.0f), fmaxf(xv.w + nv.w, 0.0f));
        uint2 pack;
        pack.x = *(uint32_t*)&h01;
        pack.y = *(uint32_t*)&h23;
        *(uint2*)(smA + c * SMA_STRIDE + lane * 4) = pack;
    }
    {
        const uint4* src = (const uint4*)(g_w + (size_t)brow * KTOT + bpart * 32);
        uint4* dst = (uint4*)(smB + brow * SMB_STRIDE + bpart * 32);
        dst[0] = src[0]; dst[1] = src[1]; dst[2] = src[2]; dst[3] = src[3];
    }
    __syncthreads();

    float acc[16][4];
    #pragma unroll
    for (int i = 0; i < 16; i++)
        #pragma unroll
        for (int j = 0; j < 4; j++) acc[i][j] = 0.0f;

    uint32_t aaddr = smA_u + (uint32_t)(((lane & 7) + ((lane >> 4) << 3)) * SMA_STRIDE
                                        + mw + ((lane >> 3) & 1) * 8) * 2u;
    // FIX (R6 bug): include the warp's n-offset (nw) in the B ldmatrix base.
    uint32_t blane = (uint32_t)((nw + (lane & 7) + ((lane >> 4) << 3)) * SMB_STRIDE
                                + ((lane >> 3) & 1) * 8) * 2u;

    int g = lane >> 2, t = lane & 3;
    int buf = 0;
    float4 xr[8], nr[8];
    uint4  br[4];

    for (int nt = 0; nt < 4; nt++) {
        for (int kc = 0; kc < 4; kc++) {
            bool lastAll = (nt == 3 && kc == 3);
            // prefetch next B chunk (reg)
            if (!lastAll) {
                int nnt = (kc == 3) ? nt + 1 : nt;
                int nkc = (kc == 3) ? 0 : kc + 1;
                const uint4* src = (const uint4*)(g_w + (size_t)(nnt * 128 + brow) * KTOT
                                                  + nkc * 64 + bpart * 32);
                br[0] = src[0]; br[1] = src[1]; br[2] = src[2]; br[3] = src[3];
            }
            // prefetch next A chunk (only during ntile 0)
            if (nt == 0 && kc < 3) {
                #pragma unroll
                for (int r = 0; r < 8; r++) {
                    int c = (kc + 1) * 64 + cl + r;
                    xr[r] = *(const float4*)(x + ((size_t)(b * CIN + c)) * HWSZ + hw0 + lane * 4);
                    nr[r] = *(const float4*)(g_noise + (size_t)c * HWSZ + hw0 + lane * 4);
                }
            }

            // MMA over smA chunk kc x smB[buf]
            uint32_t abase = aaddr + (uint32_t)(kc * 64 * SMA_STRIDE) * 2u;
            uint32_t bbase = smB_u + (uint32_t)(buf * SMB_BUF_H) * 2u + blane;
            #pragma unroll
            for (int ks = 0; ks < 4; ks++) {
                uint32_t afr[4][4];
                #pragma unroll
                for (int mi = 0; mi < 4; mi++)
                    ldsm_x4_t(afr[mi][0], afr[mi][1], afr[mi][2], afr[mi][3],
                              abase + (uint32_t)(ks * 16 * SMA_STRIDE + mi * 16) * 2u);
                uint32_t bfr[2][4];
                #pragma unroll
                for (int nip = 0; nip < 2; nip++)
                    ldsm_x4(bfr[nip][0], bfr[nip][1], bfr[nip][2], bfr[nip][3],
                            bbase + (uint32_t)(nip * 16 * SMB_STRIDE + ks * 16) * 2u);
                #pragma unroll
                for (int mi = 0; mi < 4; mi++)
                    #pragma unroll
                    for (int ni = 0; ni < 4; ni++)
                        mma16816(acc[mi * 4 + ni], afr[mi],
                                 bfr[ni >> 1][(ni & 1) * 2], bfr[ni >> 1][(ni & 1) * 2 + 1]);
            }
            __syncthreads();

            // drain prefetches to smem
            if (!lastAll) {
                uint4* dst = (uint4*)(smB + (buf ^ 1) * SMB_BUF_H + brow * SMB_STRIDE + bpart * 32);
                dst[0] = br[0]; dst[1] = br[1]; dst[2] = br[2]; dst[3] = br[3];
                buf ^= 1;
            }
            if (nt == 0 && kc < 3) {
                #pragma unroll
                for (int r = 0; r < 8; r++) {
                    __half2 h01 = __floats2half2_rn(fmaxf(xr[r].x + nr[r].x, 0.0f),
                                                    fmaxf(xr[r].y + nr[r].y, 0.0f));
                    __half2 h23 = __floats2half2_rn(fmaxf(xr[r].z + nr[r].z, 0.0f),
                                                    fmaxf(xr[r].w + nr[r].w, 0.0f));
                    uint2 pack;
                    pack.x = *(uint32_t*)&h01;
                    pack.y = *(uint32_t*)&h23;
                    *(uint2*)(smA + ((kc + 1) * 64 + cl + r) * SMA_STRIDE + lane * 4) = pack;
                }
            }
            __syncthreads();
        }

        // ---- epilogue for ntile nt: BN stats + y fp16 ----
        if (tid < 128) { sums[tid] = 0.0f; sqs[tid] = 0.0f; }
        __syncthreads();

        float lsum[8], lsq[8];
        #pragma unroll
        for (int j = 0; j < 8; j++) { lsum[j] = 0.0f; lsq[j] = 0.0f; }
        #pragma unroll
        for (int mi = 0; mi < 4; mi++) {
            #pragma unroll
            for (int ni = 0; ni < 4; ni++) {
                float c0 = acc[mi * 4 + ni][0], c1 = acc[mi * 4 + ni][1];
                float c2 = acc[mi * 4 + ni][2], c3 = acc[mi * 4 + ni][3];
                int m0 = mw + mi * 16 + g;
                int n0 = nw + ni * 8 + t * 2;
                smY[n0 * SMA_STRIDE + m0]           = __float2half_rn(c0);
                smY[(n0 + 1) * SMA_STRIDE + m0]     = __float2half_rn(c1);
                smY[n0 * SMA_STRIDE + m0 + 8]       = __float2half_rn(c2);
                smY[(n0 + 1) * SMA_STRIDE + m0 + 8] = __float2half_rn(c3);
                int j0 = ni * 2;
                lsum[j0]     += c0 + c2;  lsq[j0]     += c0 * c0 + c2 * c2;
                lsum[j0 + 1] += c1 + c3;  lsq[j0 + 1] += c1 * c1 + c3 * c3;
                acc[mi * 4 + ni][0] = 0.0f; acc[mi * 4 + ni][1] = 0.0f;
                acc[mi * 4 + ni][2] = 0.0f; acc[mi * 4 + ni][3] = 0.0f;
            }
        }
        #pragma unroll
        for (int j = 0; j < 8; j++) {
            #pragma unroll
            for (int off = 4; off <= 16; off <<= 1) {
                lsum[j] += __shfl_xor_sync(0xFFFFFFFFu, lsum[j], off);
                lsq[j]  += __shfl_xor_sync(0xFFFFFFFFu, lsq[j], off);
            }
        }
        if (g == 0) {
            #pragma unroll
            for (int j = 0; j < 8; j++) {
                int n = nw + (j >> 1) * 8 + t * 2 + (j & 1);
                atomicAdd(&sums[n], lsum[j]);
                atomicAdd(&sqs[n],  lsq[j]);
            }
        }
        __syncthreads();

        #pragma unroll
        for (int i = 0; i < 16; i++) {
            int n = warp * 16 + i;
            uint2 v = *(uint2*)(smY + n * SMA_STRIDE + lane * 4);
            *(uint2*)(g_y + ((size_t)(b * COUT + nt * 128 + n)) * HWSZ + hw0 + lane * 4) = v;
        }
        if (tid < 128) {
            atomicAdd(&g_sum[nt * 128 + tid], sums[tid]);
            atomicAdd(&g_sq[nt * 128 + tid],  sqs[tid]);
        }
        if (nt < 3) __syncthreads();
    }
}

// ============================ kernel 2: BN normalize ============================
// Reverse traversal: read y starting from its most-recently-written end so the
// ~126MB L2 still holds it (y = 134MB). 32B/thread.
__global__ void k_norm(float* __restrict__ out,
                       const float* __restrict__ gamma,
                       const float* __restrict__ beta) {
    size_t lin  = (size_t)blockIdx.x * blockDim.x + threadIdx.x;   // 8,388,608 threads
    size_t idx8 = (8388608u - 1u) - lin;                           // 8-elem group, reversed
    int o = (int)((idx8 >> 9) & (COUT - 1));                       // 512 groups per (b,o) slab
    float mean = g_sum[o] * (1.0f / NPIX);
    float var  = g_sq[o]  * (1.0f / NPIX) - mean * mean;
    float inv  = rsqrtf(var + 1e-5f);
    float ga = gamma[o] * inv;
    float be = beta[o] - mean * ga;
    uint4 p = __ldcs((const uint4*)(g_y + idx8 * 8));
    float4 o0, o1;
    {
        float2 f0 = __half22float2(*(__half2*)&p.x);
        float2 f1 = __half22float2(*(__half2*)&p.y);
        o0.x = f0.x * ga + be; o0.y = f0.y * ga + be;
        o0.z = f1.x * ga + be; o0.w = f1.y * ga + be;
    }
    {
        float2 f2 = __half22float2(*(__half2*)&p.z);
        float2 f3 = __half22float2(*(__half2*)&p.w);
        o1.x = f2.x * ga + be; o1.y = f2.y * ga + be;
        o1.z = f3.x * ga + be; o1.w = f3.y * ga + be;
    }
    __stcs(((float4*)out) + idx8 * 2,     o0);
    __stcs(((float4*)out) + idx8 * 2 + 1, o1);
}

// ============================ launcher ============================
extern "C" void kernel_launch(void* const* d_in, const int* in_sizes, int n_in,
                              void* d_out, int out_size) {
    const float* x     = (const float*)d_in[0];
    const float* w     = (const float*)d_in[1];
    // d_in[2] = conv_b: exactly cancelled by BatchNorm mean subtraction.
    const float* gamma = (const float*)d_in[3];
    const float* beta  = (const float*)d_in[4];
    float* out = (float*)d_out;

    cudaFuncSetAttribute(k_gemm, cudaFuncAttributeMaxDynamicSharedMemorySize, SM_TOTAL);

    k_init<<<4096, 256>>>(w);                 // noise table + fp16 W + zero stats
    k_gemm<<<1024, 256, SM_TOTAL>>>(x);       // fused noise+relu+GEMM+BN-stats, y fp16
    k_norm<<<32768, 256>>>(out, gamma, beta); // finalize BN -> fp32 out (reversed)
}

// round 8
// speedup vs baseline: 1.3876x; 1.1863x over previous
#include <cuda_runtime.h>
#include <cuda_fp16.h>
#include <cstdint>

// ============================ problem sizes ============================
#define BB    32
#define CIN   256
#define COUT  512
#define HWSZ  4096                  // 64*64
#define KTOT  256
#define NPIX  131072.0f             // B*H*W per channel

// ============================ device scratch ============================
__device__ __align__(128) float  g_noise[CIN * HWSZ];            // 4 MB
__device__ __align__(128) __half g_w[COUT * KTOT];               // 256 KB  [o][c]
__device__ __align__(128) __half g_y[(size_t)BB * COUT * HWSZ];  // 134 MB
__device__ float g_sum[COUT];
__device__ float g_sq[COUT];

// ============================ helpers ============================
__device__ __forceinline__ uint32_t smem_u32(const void* p) {
    uint32_t a;
    asm("{ .reg .u64 t; cvta.to.shared.u64 t, %1; cvt.u32.u64 %0, t; }" : "=r"(a) : "l"(p));
    return a;
}
__device__ __forceinline__ void ldsm_x4(uint32_t& r0, uint32_t& r1, uint32_t& r2, uint32_t& r3,
                                        uint32_t addr) {
    asm volatile("ldmatrix.sync.aligned.m8n8.x4.shared.b16 {%0,%1,%2,%3}, [%4];"
                 : "=r"(r0), "=r"(r1), "=r"(r2), "=r"(r3) : "r"(addr));
}
__device__ __forceinline__ void ldsm_x4_t(uint32_t& r0, uint32_t& r1, uint32_t& r2, uint32_t& r3,
                                          uint32_t addr) {
    asm volatile("ldmatrix.sync.aligned.m8n8.x4.trans.shared.b16 {%0,%1,%2,%3}, [%4];"
                 : "=r"(r0), "=r"(r1), "=r"(r2), "=r"(r3) : "r"(addr));
}
__device__ __forceinline__ void mma16816(float* d, const uint32_t* a, uint32_t b0, uint32_t b1) {
    asm volatile("mma.sync.aligned.m16n8k16.row.col.f32.f16.f16.f32 "
                 "{%0,%1,%2,%3}, {%4,%5,%6,%7}, {%8,%9}, {%0,%1,%2,%3};"
                 : "+f"(d[0]), "+f"(d[1]), "+f"(d[2]), "+f"(d[3])
                 : "r"(a[0]), "r"(a[1]), "r"(a[2]), "r"(a[3]), "r"(b0), "r"(b1));
}

// ============================ kernel 0: init ============================
struct LCGTab { unsigned A[21]; unsigned C[21]; };
__host__ __device__ constexpr LCGTab make_tab() {
    LCGTab t{};
    unsigned a = 65539u, c = 1u;
    for (int j = 0; j < 21; j++) {
        t.A[j] = a; t.C[j] = c;
        unsigned c2 = a * c + c;
        a = a * a; c = c2;
    }
    return t;
}
__global__ void k_init(const float* __restrict__ w) {
    constexpr LCGTab T = make_tab();
    int i = blockIdx.x * blockDim.x + threadIdx.x;   // 0 .. 1048575
    unsigned n = (unsigned)i + 1u;
    unsigned rA = 1u, rC = 0u;
    #pragma unroll
    for (int j = 0; j < 21; j++) {
        if ((n >> j) & 1u) { rA = T.A[j] * rA; rC = T.A[j] * rC + T.C[j]; }
    }
    unsigned seed = rA * 12345u + rC;
    g_noise[i] = (float)seed * (float)(0.1 / 4294967295.0);

    if (i < COUT * KTOT) g_w[i] = __float2half_rn(w[i]);
    if (i < COUT) { g_sum[i] = 0.0f; g_sq[i] = 0.0f; }
}

// ============================ kernel 1: fused GEMM v3 (2 CTAs/SM) ============================
// CTA: 128 m-pixels x all 512 out-channels. A = relu(x+noise) fp16, full-K in smem
// (x read from DRAM once). B single-buffered per phase from L2. Epilogue reuses the
// smB region in two 64-n passes. smem 87KB + regs<=128 -> 2 CTAs/SM; the co-resident
// CTA's MMA hides this CTA's staging / epilogue / barrier time.
#define SMA_OFF    0                       // [256 k][136 m] half = 69632 B
#define SMB_OFF    69632                   // [128 n][72 k] half = 18432 B
#define STAT_OFF   88064                   // 256 floats = 1024 B
#define SM_TOTAL   89088
#define SMA_STRIDE 136
#define SMB_STRIDE 72

__global__ void __launch_bounds__(256, 2) k_gemm(const float* __restrict__ x) {
    extern __shared__ char smem[];
    __half* smA = (__half*)(smem + SMA_OFF);
    __half* smB = (__half*)(smem + SMB_OFF);
    float*  sums = (float*)(smem + STAT_OFF);
    float*  sqs  = sums + 128;
    uint32_t smA_u = smem_u32(smA);
    uint32_t smB_u = smem_u32(smB);

    int tid = threadIdx.x, warp = tid >> 5, lane = tid & 31;
    int mtile = blockIdx.x;            // 0..1023
    int b   = mtile >> 5;
    int hw0 = (mtile & 31) << 7;       // 128-pixel contiguous hw slab

    int mw = (warp >> 2) * 64;         // warp m offset
    int nw = (warp & 3) * 32;          // warp n offset within 128-n tile
    int cl = warp * 8;                 // channels staged per warp per chunk
    int brow = tid & 127, bpart = tid >> 7;

    float acc[16][4];
    #pragma unroll
    for (int i = 0; i < 16; i++)
        #pragma unroll
        for (int j = 0; j < 4; j++) acc[i][j] = 0.0f;

    uint32_t aaddr = smA_u + (uint32_t)(((lane & 7) + ((lane >> 4) << 3)) * SMA_STRIDE
                                        + mw + ((lane >> 3) & 1) * 8) * 2u;
    uint32_t blane = smB_u + (uint32_t)((nw + (lane & 7) + ((lane >> 4) << 3)) * SMB_STRIDE
                                        + ((lane >> 3) & 1) * 8) * 2u;
    int g = lane >> 2, t = lane & 3;

    for (int nt = 0; nt < 4; nt++) {
        for (int kc = 0; kc < 4; kc++) {
            // smB (and, for nt==0, smA chunk kc) are free here (sync at end of prev phase)
            if (nt == 0) {
                #pragma unroll
                for (int r = 0; r < 8; r++) {
                    int c = kc * 64 + cl + r;
                    float4 xv = *(const float4*)(x + ((size_t)(b * CIN + c)) * HWSZ + hw0 + lane * 4);
                    float4 nv = *(const float4*)(g_noise + (size_t)c * HWSZ + hw0 + lane * 4);
                    __half2 h01 = __floats2half2_rn(fmaxf(xv.x + nv.x, 0.0f), fmaxf(xv.y + nv.y, 0.0f));
                    __half2 h23 = __floats2half2_rn(fmaxf(xv.z + nv.z, 0.0f), fmaxf(xv.w + nv.w, 0.0f));
                    uint2 pack;
                    pack.x = *(uint32_t*)&h01;
                    pack.y = *(uint32_t*)&h23;
                    *(uint2*)(smA + c * SMA_STRIDE + lane * 4) = pack;
                }
            }
            {   // B tile for (nt, kc): L2-resident weights
                const uint4* src = (const uint4*)(g_w + (size_t)(nt * 128 + brow) * KTOT
                                                  + kc * 64 + bpart * 32);
                uint4* dst = (uint4*)(smB + brow * SMB_STRIDE + bpart * 32);
                dst[0] = src[0]; dst[1] = src[1]; dst[2] = src[2]; dst[3] = src[3];
            }
            __syncthreads();

            uint32_t abase = aaddr + (uint32_t)(kc * 64 * SMA_STRIDE) * 2u;
            #pragma unroll
            for (int ks = 0; ks < 4; ks++) {
                uint32_t afr[4][4];
                #pragma unroll
                for (int mi = 0; mi < 4; mi++)
                    ldsm_x4_t(afr[mi][0], afr[mi][1], afr[mi][2], afr[mi][3],
                              abase + (uint32_t)(ks * 16 * SMA_STRIDE + mi * 16) * 2u);
                uint32_t bfr[2][4];
                #pragma unroll
                for (int nip = 0; nip < 2; nip++)
                    ldsm_x4(bfr[nip][0], bfr[nip][1], bfr[nip][2], bfr[nip][3],
                            blane + (uint32_t)(nip * 16 * SMB_STRIDE + ks * 16) * 2u);
                #pragma unroll
                for (int mi = 0; mi < 4; mi++)
                    #pragma unroll
                    for (int ni = 0; ni < 4; ni++)
                        mma16816(acc[mi * 4 + ni], afr[mi],
                                 bfr[ni >> 1][(ni & 1) * 2], bfr[ni >> 1][(ni & 1) * 2 + 1]);
            }
            __syncthreads();
        }

        // ---- epilogue for ntile nt: BN stats + y fp16 in two 64-n passes via smB ----
        if (tid < 128) { sums[tid] = 0.0f; sqs[tid] = 0.0f; }

        float lsum[8], lsq[8];
        #pragma unroll
        for (int j = 0; j < 8; j++) { lsum[j] = 0.0f; lsq[j] = 0.0f; }
        #pragma unroll
        for (int mi = 0; mi < 4; mi++)
            #pragma unroll
            for (int ni = 0; ni < 4; ni++) {
                float c0 = acc[mi * 4 + ni][0], c1 = acc[mi * 4 + ni][1];
                float c2 = acc[mi * 4 + ni][2], c3 = acc[mi * 4 + ni][3];
                int j0 = ni * 2;
                lsum[j0]     += c0 + c2;  lsq[j0]     += c0 * c0 + c2 * c2;
                lsum[j0 + 1] += c1 + c3;  lsq[j0 + 1] += c1 * c1 + c3 * c3;
            }
        #pragma unroll
        for (int j = 0; j < 8; j++) {
            #pragma unroll
            for (int off = 4; off <= 16; off <<= 1) {
                lsum[j] += __shfl_xor_sync(0xFFFFFFFFu, lsum[j], off);
                lsq[j]  += __shfl_xor_sync(0xFFFFFFFFu, lsq[j], off);
            }
        }
        __syncthreads();                      // stat zeroing visible; smB free
        if (g == 0) {
            #pragma unroll
            for (int j = 0; j < 8; j++) {
                int n = nw + (j >> 1) * 8 + t * 2 + (j & 1);
                atomicAdd(&sums[n], lsum[j]);
                atomicAdd(&sqs[n],  lsq[j]);
            }
        }

        __half* smY = smB;                    // [64 n][136 m] transpose buffer
        #pragma unroll
        for (int p = 0; p < 2; p++) {
            if ((warp & 2) == p * 2) {        // warps owning n in [64p, 64p+64)
                int nl = nw - p * 64;         // 0 or 32
                #pragma unroll
                for (int mi = 0; mi < 4; mi++)
                    #pragma unroll
                    for (int ni = 0; ni < 4; ni++) {
                        float c0 = acc[mi * 4 + ni][0], c1 = acc[mi * 4 + ni][1];
                        float c2 = acc[mi * 4 + ni][2], c3 = acc[mi * 4 + ni][3];
                        int m0 = mw + mi * 16 + g;
                        int n0 = nl + ni * 8 + t * 2;
                        smY[n0 * SMA_STRIDE + m0]           = __float2half_rn(c0);
                        smY[(n0 + 1) * SMA_STRIDE + m0]     = __float2half_rn(c1);
                        smY[n0 * SMA_STRIDE + m0 + 8]       = __float2half_rn(c2);
                        smY[(n0 + 1) * SMA_STRIDE + m0 + 8] = __float2half_rn(c3);
                    }
            }
            __syncthreads();
            // all 8 warps store 64 rows (8 rows each), coalesced 256B per row
            #pragma unroll
            for (int i = 0; i < 8; i++) {
                int n = warp * 8 + i;
                uint2 v = *(uint2*)(smY + n * SMA_STRIDE + lane * 4);
                *(uint2*)(g_y + ((size_t)(b * COUT + nt * 128 + p * 64 + n)) * HWSZ
                          + hw0 + lane * 4) = v;
            }
            __syncthreads();
        }

        if (tid < 128) {
            atomicAdd(&g_sum[nt * 128 + tid], sums[tid]);
            atomicAdd(&g_sq[nt * 128 + tid],  sqs[tid]);
        }
        // reset acc for next ntile
        #pragma unroll
        for (int i = 0; i < 16; i++)
            #pragma unroll
            for (int j = 0; j < 4; j++) acc[i][j] = 0.0f;
        // NOTE: next nt's first smB write happens after the phase-entry logic;
        // the trailing __syncthreads() above already ordered smY reads before it.
    }
}

// ============================ kernel 2: BN normalize ============================
// Reverse traversal: read y starting from its most-recently-written end so the
// ~126MB L2 still holds it (y = 134MB). 32B/thread.
__global__ void k_norm(float* __restrict__ out,
                       const float* __restrict__ gamma,
                       const float* __restrict__ beta) {
    size_t lin  = (size_t)blockIdx.x * blockDim.x + threadIdx.x;   // 8,388,608 threads
    size_t idx8 = (8388608u - 1u) - lin;                           // 8-elem group, reversed
    int o = (int)((idx8 >> 9) & (COUT - 1));                       // 512 groups per (b,o) slab
    float mean = g_sum[o] * (1.0f / NPIX);
    float var  = g_sq[o]  * (1.0f / NPIX) - mean * mean;
    float inv  = rsqrtf(var + 1e-5f);
    float ga = gamma[o] * inv;
    float be = beta[o] - mean * ga;
    uint4 p = __ldcs((const uint4*)(g_y + idx8 * 8));
    float4 o0, o1;
    {
        float2 f0 = __half22float2(*(__half2*)&p.x);
        float2 f1 = __half22float2(*(__half2*)&p.y);
        o0.x = f0.x * ga + be; o0.y = f0.y * ga + be;
        o0.z = f1.x * ga + be; o0.w = f1.y * ga + be;
    }
    {
        float2 f2 = __half22float2(*(__half2*)&p.z);
        float2 f3 = __half22float2(*(__half2*)&p.w);
        o1.x = f2.x * ga + be; o1.y = f2.y * ga + be;
        o1.z = f3.x * ga + be; o1.w = f3.y * ga + be;
    }
    __stcs(((float4*)out) + idx8 * 2,     o0);
    __stcs(((float4*)out) + idx8 * 2 + 1, o1);
}

// ============================ launcher ============================
extern "C" void kernel_launch(void* const* d_in, const int* in_sizes, int n_in,
                              void* d_out, int out_size) {
    const float* x     = (const float*)d_in[0];
    const float* w     = (const float*)d_in[1];
    // d_in[2] = conv_b: exactly cancelled by BatchNorm mean subtraction.
    const float* gamma = (const float*)d_in[3];
    const float* beta  = (const float*)d_in[4];
    float* out = (float*)d_out;

    cudaFuncSetAttribute(k_gemm, cudaFuncAttributeMaxDynamicSharedMemorySize, SM_TOTAL);

    k_init<<<4096, 256>>>(w);                 // noise table + fp16 W + zero stats
    k_gemm<<<1024, 256, SM_TOTAL>>>(x);       // fused noise+relu+GEMM+BN-stats, y fp16
    k_norm<<<32768, 256>>>(out, gamma, beta); // finalize BN -> fp32 out (reversed)
}